// round 4
// baseline (speedup 1.0000x reference)
#include <cuda_runtime.h>
#include <cuda_bf16.h>

// Problem constants: B=1, H=W=64 (P=4096 tokens), C=768, nH=12, hd=64.
#define PTOK 4096
#define CDIM 768
#define NH   12
#define HD   64

// Scratch (no cudaMalloc allowed) — zero-init bss.
__device__ float g_q[NH * PTOK * HD];
__device__ float g_k[NH * PTOK * HD];
__device__ float g_v[NH * PTOK * HD];
__device__ float g_relh[NH * PTOK * HD];   // [n][p][kh]
__device__ float g_relw[NH * PTOK * HD];   // [n][p][kw]  (p encodes (h,w) of the *query* arg)
__device__ float g_o[PTOK * NH * HD];      // [p][n*64+d]

// ---------------------------------------------------------------------------
// Tiled fp32 GEMM: out[m][o] = sum_c A[m][c] * Wt[o][c] + bias[o]
// mode 0: write per-head layout out[(o>>6)*P*HD + m*HD + (o&63)]
// mode 1: write plain out[m*768 + o]
// ---------------------------------------------------------------------------
__global__ void gemm_kernel(const float* __restrict__ A,
                            const float* __restrict__ Wt,
                            const float* __restrict__ bias,
                            float* __restrict__ out, int mode)
{
    __shared__ float As[64][16];
    __shared__ float Bs[16][64];
    const int tid = threadIdx.x;
    const int tx = tid & 15, ty = tid >> 4;
    const int m0 = blockIdx.y * 64;
    const int n0 = blockIdx.x * 64;

    float acc[4][4] = {};

    for (int k0 = 0; k0 < CDIM; k0 += 16) {
        {   // A tile (64x16)
            int r = tid >> 2, c = (tid & 3) * 4;
            const float4 av = *(const float4*)(A + (size_t)(m0 + r) * CDIM + k0 + c);
            As[r][c + 0] = av.x; As[r][c + 1] = av.y;
            As[r][c + 2] = av.z; As[r][c + 3] = av.w;
        }
        {   // W tile transposed
            int o = tid >> 2, c = (tid & 3) * 4;
            const float4 wv = *(const float4*)(Wt + (size_t)(n0 + o) * CDIM + k0 + c);
            Bs[c + 0][o] = wv.x; Bs[c + 1][o] = wv.y;
            Bs[c + 2][o] = wv.z; Bs[c + 3][o] = wv.w;
        }
        __syncthreads();
#pragma unroll
        for (int kk = 0; kk < 16; kk++) {
            float a[4], b[4];
#pragma unroll
            for (int i = 0; i < 4; i++) a[i] = As[ty * 4 + i][kk];
#pragma unroll
            for (int j = 0; j < 4; j++) b[j] = Bs[kk][tx * 4 + j];
#pragma unroll
            for (int i = 0; i < 4; i++)
#pragma unroll
                for (int j = 0; j < 4; j++) acc[i][j] += a[i] * b[j];
        }
        __syncthreads();
    }

#pragma unroll
    for (int i = 0; i < 4; i++) {
        int m = m0 + ty * 4 + i;
#pragma unroll
        for (int j = 0; j < 4; j++) {
            int o = n0 + tx * 4 + j;
            float val = acc[i][j] + bias[o];
            if (mode == 0)
                out[(size_t)(o >> 6) * (PTOK * HD) + (size_t)m * HD + (o & 63)] = val;
            else
                out[(size_t)m * CDIM + o] = val;
        }
    }
}

// ---------------------------------------------------------------------------
// rel_h / rel_w precompute.
// g_relh[n][p][kh] = q[n][p] . rel_pos_h[(h_p - kh + 63)]   (h_p = p/64)
// g_relw[n][p][kw] = q[n][p] . rel_pos_w[(w_p - kw + 63)]   (w_p = p%64)
// ---------------------------------------------------------------------------
__global__ void relpos_kernel(const float* __restrict__ rph,
                              const float* __restrict__ rpw)
{
    const int b = blockIdx.x;
    const int n = b >> 12;
    const int p = b & 4095;
    const int h = p >> 6, w = p & 63;
    const int t = threadIdx.x;

    __shared__ float qs[64];
    qs[t] = g_q[(size_t)n * PTOK * HD + (size_t)p * HD + t];
    __syncthreads();

    const float* rh = rph + (size_t)(h - t + 63) * HD;
    const float* rw = rpw + (size_t)(w - t + 63) * HD;
    float sh = 0.f, sw = 0.f;
#pragma unroll
    for (int c = 0; c < HD; c++) {
        float qc = qs[c];
        sh += qc * rh[c];
        sw += qc * rw[c];
    }
    g_relh[(size_t)n * PTOK * HD + (size_t)p * HD + t] = sh;
    g_relw[(size_t)n * PTOK * HD + (size_t)p * HD + t] = sw;
}

// ---------------------------------------------------------------------------
// Flash attention with the reference's (broadcast-quirk) rel-pos bias:
//   bias[qh,qw,kh,kw] = rel_h[qh,qw,kh] + rel_w[qh,kh,kw]
// Query tile qb has qh=qb fixed, rows = qw. Key block kb has kh=kb, cols = kw.
//   -> rel_h term: per-row scalar   g_relh[n][qb*64+row][kb]
//   -> rel_w term: per-col scalar   g_relw[n][qb*64+kb][col]  (row-independent!)
// ---------------------------------------------------------------------------
__global__ void flash_kernel(float scale)
{
    extern __shared__ float sm[];
    float* Qs = sm;            // 64*65
    float* Ks = sm + 4160;
    float* Vs = sm + 8320;
    float* Ps = sm + 12480;

    const int n  = blockIdx.y;
    const int qb = blockIdx.x;
    const int tid = threadIdx.x;
    const int tx = tid & 15, ty = tid >> 4;

    const float* qbase = g_q + (size_t)n * PTOK * HD + (size_t)qb * 64 * HD;

    for (int e = tid; e < 1024; e += 256) {
        int off = e * 4;
        int r = off >> 6, c = off & 63;
        float4 v = *(const float4*)(qbase + off);
        Qs[r * 65 + c + 0] = v.x; Qs[r * 65 + c + 1] = v.y;
        Qs[r * 65 + c + 2] = v.z; Qs[r * 65 + c + 3] = v.w;
    }

    const float* rwbase = g_relw + (size_t)n * PTOK * HD + (size_t)(qb * 64) * HD;
    const float* rhbase = g_relh + (size_t)n * PTOK * HD + (size_t)(qb * 64) * HD;

    float m[4], l[4], acc[4][4] = {};
#pragma unroll
    for (int i = 0; i < 4; i++) { m[i] = -1e30f; l[i] = 0.f; }

    for (int kb = 0; kb < 64; kb++) {
        const float* kbase = g_k + (size_t)n * PTOK * HD + (size_t)kb * 64 * HD;
        const float* vbase = g_v + (size_t)n * PTOK * HD + (size_t)kb * 64 * HD;

        __syncthreads();
        for (int e = tid; e < 1024; e += 256) {
            int off = e * 4;
            int r = off >> 6, c = off & 63;
            float4 kv = *(const float4*)(kbase + off);
            Ks[r * 65 + c + 0] = kv.x; Ks[r * 65 + c + 1] = kv.y;
            Ks[r * 65 + c + 2] = kv.z; Ks[r * 65 + c + 3] = kv.w;
            float4 vv = *(const float4*)(vbase + off);
            Vs[r * 65 + c + 0] = vv.x; Vs[r * 65 + c + 1] = vv.y;
            Vs[r * 65 + c + 2] = vv.z; Vs[r * 65 + c + 3] = vv.w;
        }
        __syncthreads();

        // S = Q K^T
        float s[4][4] = {};
#pragma unroll 16
        for (int kk = 0; kk < 64; kk++) {
            float a[4], b[4];
#pragma unroll
            for (int i = 0; i < 4; i++) a[i] = Qs[(ty * 4 + i) * 65 + kk];
#pragma unroll
            for (int j = 0; j < 4; j++) b[j] = Ks[(tx * 4 + j) * 65 + kk];
#pragma unroll
            for (int i = 0; i < 4; i++)
#pragma unroll
                for (int j = 0; j < 4; j++) s[i][j] += a[i] * b[j];
        }

        // rel_w term for this key block: row-independent, per column.
        // Uses the quirk row p' = qb*64 + kb.
        float rwv[4];
        {
            const float4 rv = *(const float4*)(rwbase + (size_t)kb * HD + tx * 4);
            rwv[0] = rv.x; rwv[1] = rv.y; rwv[2] = rv.z; rwv[3] = rv.w;
        }

        // bias + online softmax
#pragma unroll
        for (int i = 0; i < 4; i++) {
            float rh = rhbase[(ty * 4 + i) * HD + kb];
            float mx = -1e30f;
#pragma unroll
            for (int j = 0; j < 4; j++) {
                s[i][j] = s[i][j] * scale + rh + rwv[j];
                mx = fmaxf(mx, s[i][j]);
            }
#pragma unroll
            for (int off = 8; off; off >>= 1)
                mx = fmaxf(mx, __shfl_xor_sync(0xffffffffu, mx, off));
            float mnew = fmaxf(m[i], mx);
            float corr = __expf(m[i] - mnew);
            float sum = 0.f;
#pragma unroll
            for (int j = 0; j < 4; j++) {
                s[i][j] = __expf(s[i][j] - mnew);
                sum += s[i][j];
            }
#pragma unroll
            for (int off = 8; off; off >>= 1)
                sum += __shfl_xor_sync(0xffffffffu, sum, off);
            l[i] = l[i] * corr + sum;
            m[i] = mnew;
#pragma unroll
            for (int j = 0; j < 4; j++) acc[i][j] *= corr;
#pragma unroll
            for (int j = 0; j < 4; j++)
                Ps[(ty * 4 + i) * 65 + tx * 4 + j] = s[i][j];
        }
        __syncthreads();

        // acc += P V
#pragma unroll 16
        for (int j0 = 0; j0 < 64; j0++) {
            float pv[4], vv[4];
#pragma unroll
            for (int i = 0; i < 4; i++) pv[i] = Ps[(ty * 4 + i) * 65 + j0];
#pragma unroll
            for (int j = 0; j < 4; j++) vv[j] = Vs[j0 * 65 + tx * 4 + j];
#pragma unroll
            for (int i = 0; i < 4; i++)
#pragma unroll
                for (int j = 0; j < 4; j++) acc[i][j] += pv[i] * vv[j];
        }
    }

#pragma unroll
    for (int i = 0; i < 4; i++) {
        int q = qb * 64 + ty * 4 + i;
        float inv = 1.f / l[i];
#pragma unroll
        for (int j = 0; j < 4; j++)
            g_o[(size_t)q * CDIM + n * HD + tx * 4 + j] = acc[i][j] * inv;
    }
}

// ---------------------------------------------------------------------------
extern "C" void kernel_launch(void* const* d_in, const int* in_sizes, int n_in,
                              void* d_out, int out_size)
{
    const float* x   = (const float*)d_in[0];
    const float* wq  = (const float*)d_in[1];
    const float* bq  = (const float*)d_in[2];
    const float* wk  = (const float*)d_in[3];
    const float* bk  = (const float*)d_in[4];
    const float* wv  = (const float*)d_in[5];
    const float* bv  = (const float*)d_in[6];
    const float* rph = (const float*)d_in[7];
    const float* rpw = (const float*)d_in[8];
    const float* pw  = (const float*)d_in[9];
    const float* pb  = (const float*)d_in[10];
    float* out = (float*)d_out;

    float *qp, *kp, *vp, *op;
    cudaGetSymbolAddress((void**)&qp, g_q);
    cudaGetSymbolAddress((void**)&kp, g_k);
    cudaGetSymbolAddress((void**)&vp, g_v);
    cudaGetSymbolAddress((void**)&op, g_o);

    cudaFuncSetAttribute(flash_kernel,
                         cudaFuncAttributeMaxDynamicSharedMemorySize, 66560);

    dim3 gemm_grid(CDIM / 64, PTOK / 64);   // (12, 64)

    gemm_kernel<<<gemm_grid, 256>>>(x, wq, bq, qp, 0);
    gemm_kernel<<<gemm_grid, 256>>>(x, wk, bk, kp, 0);
    gemm_kernel<<<gemm_grid, 256>>>(x, wv, bv, vp, 0);

    relpos_kernel<<<NH * PTOK, 64>>>(rph, rpw);

    flash_kernel<<<dim3(64, NH), 256, 66560>>>(0.125f);  // hd^-0.5

    gemm_kernel<<<gemm_grid, 256>>>(op, pw, pb, out, 1);
}

// round 5
// speedup vs baseline: 2.1652x; 2.1652x over previous
#include <cuda_runtime.h>
#include <cuda_fp16.h>
#include <cuda_bf16.h>

// Problem constants: B=1, H=W=64 (P=4096 tokens), C=768, nH=12, hd=64.
#define PTOK 4096
#define CDIM 768
#define NH   12
#define HD   64
#define LOG2E 1.44269504088896f

// ---------------------------------------------------------------------------
// Scratch (__device__ globals; no cudaMalloc allowed)
// ---------------------------------------------------------------------------
__device__ __half g_hx [PTOK * CDIM];       // x in fp16
__device__ __half g_hwq[CDIM * CDIM];
__device__ __half g_hwk[CDIM * CDIM];
__device__ __half g_hwv[CDIM * CDIM];
__device__ __half g_hpw[CDIM * CDIM];
__device__ __half g_qh [NH * PTOK * HD];    // per-head q/k/v fp16
__device__ __half g_kh [NH * PTOK * HD];
__device__ __half g_vh [NH * PTOK * HD];
__device__ __half g_oh [PTOK * CDIM];       // attention out [p][n*64+d]
__device__ float  g_relh[NH * PTOK * HD];   // [n][p][kh]  (pre-scaled by log2e)
__device__ float  g_relw[NH * PTOK * HD];   // [n][p][kw]  (pre-scaled by log2e)

// ---------------------------------------------------------------------------
// helpers
// ---------------------------------------------------------------------------
__device__ __forceinline__ unsigned su32(const void* p) {
    return (unsigned)__cvta_generic_to_shared(p);
}
__device__ __forceinline__ void ldsm_x4(unsigned& r0, unsigned& r1,
                                        unsigned& r2, unsigned& r3, unsigned a) {
    asm volatile("ldmatrix.sync.aligned.m8n8.x4.shared.b16 {%0,%1,%2,%3}, [%4];"
                 : "=r"(r0), "=r"(r1), "=r"(r2), "=r"(r3) : "r"(a));
}
__device__ __forceinline__ void ldsm_x2(unsigned& r0, unsigned& r1, unsigned a) {
    asm volatile("ldmatrix.sync.aligned.m8n8.x2.shared.b16 {%0,%1}, [%2];"
                 : "=r"(r0), "=r"(r1) : "r"(a));
}
__device__ __forceinline__ void ldsm_x2t(unsigned& r0, unsigned& r1, unsigned a) {
    asm volatile("ldmatrix.sync.aligned.m8n8.x2.trans.shared.b16 {%0,%1}, [%2];"
                 : "=r"(r0), "=r"(r1) : "r"(a));
}
__device__ __forceinline__ void mma16816(float* c, const unsigned* a,
                                         unsigned b0, unsigned b1) {
    asm volatile(
        "mma.sync.aligned.m16n8k16.row.col.f32.f16.f16.f32 "
        "{%0,%1,%2,%3},{%4,%5,%6,%7},{%8,%9},{%0,%1,%2,%3};"
        : "+f"(c[0]), "+f"(c[1]), "+f"(c[2]), "+f"(c[3])
        : "r"(a[0]), "r"(a[1]), "r"(a[2]), "r"(a[3]), "r"(b0), "r"(b1));
}
__device__ __forceinline__ float ex2(float x) {
    float r; asm("ex2.approx.f32 %0, %1;" : "=f"(r) : "f"(x)); return r;
}
__device__ __forceinline__ unsigned pack2(float x, float y) {
    __half2 h = __floats2half2_rn(x, y);
    return *reinterpret_cast<unsigned*>(&h);
}

// ---------------------------------------------------------------------------
// fp32 -> fp16 conversion (4 elems/thread)
// ---------------------------------------------------------------------------
__global__ void f2h_kernel(const float* __restrict__ in, __half* __restrict__ out, int n)
{
    int i = (blockIdx.x * 256 + threadIdx.x) * 4;
    if (i < n) {
        float4 v = *(const float4*)(in + i);
        *(__half2*)(out + i)     = __floats2half2_rn(v.x, v.y);
        *(__half2*)(out + i + 2) = __floats2half2_rn(v.z, v.w);
    }
}

// ---------------------------------------------------------------------------
// fp16 tensor-core GEMM: out[m][o] = sum_c A[m][c] * W[o][c] + bias[o]
// A: [4096][768] half, W: [768][768] half (c contiguous). fp32 accum.
// mode 0: half out, per-head layout [(o>>6)*P + m][o&63]
// mode 1: fp32 out, plain [m][768]
// BM=128, BN=64, BK=32, 256 threads, warp tile 32x32.
// ---------------------------------------------------------------------------
__global__ __launch_bounds__(256) void hgemm_kernel(
    const __half* __restrict__ A, const __half* __restrict__ W,
    const float* __restrict__ bias, void* __restrict__ out, int mode)
{
    __shared__ __half As[128 * 40];
    __shared__ __half Bs[64 * 40];
    const int tid = threadIdx.x;
    const int warp = tid >> 5, lane = tid & 31;
    const int m0 = blockIdx.y * 128;
    const int n0 = blockIdx.x * 64;
    const int wm = (warp >> 1) * 32;
    const int wn = (warp & 1) * 32;

    float acc[2][4][4] = {};

    for (int k0 = 0; k0 < CDIM; k0 += 32) {
#pragma unroll
        for (int i = 0; i < 2; i++) {
            int v = tid + i * 256;
            int r = v >> 2, c = (v & 3) * 8;
            *(uint4*)&As[r * 40 + c] = *(const uint4*)&A[(size_t)(m0 + r) * CDIM + k0 + c];
        }
        {
            int r = tid >> 2, c = (tid & 3) * 8;
            *(uint4*)&Bs[r * 40 + c] = *(const uint4*)&W[(size_t)(n0 + r) * CDIM + k0 + c];
        }
        __syncthreads();
#pragma unroll
        for (int ks = 0; ks < 2; ks++) {
            unsigned a[2][4];
#pragma unroll
            for (int mi = 0; mi < 2; mi++) {
                unsigned addr = su32(&As[(wm + mi * 16 + (lane & 15)) * 40
                                         + ks * 16 + (lane >> 4) * 8]);
                ldsm_x4(a[mi][0], a[mi][1], a[mi][2], a[mi][3], addr);
            }
#pragma unroll
            for (int j = 0; j < 4; j++) {
                unsigned b0, b1;
                unsigned addr = su32(&Bs[(wn + j * 8 + (lane & 7)) * 40
                                         + ks * 16 + ((lane >> 3) & 1) * 8]);
                ldsm_x2(b0, b1, addr);
#pragma unroll
                for (int mi = 0; mi < 2; mi++) mma16816(acc[mi][j], a[mi], b0, b1);
            }
        }
        __syncthreads();
    }

    const int r0 = lane >> 2, q2 = (lane & 3) * 2;
#pragma unroll
    for (int mi = 0; mi < 2; mi++) {
        int rowa = m0 + wm + mi * 16 + r0;
        int rowb = rowa + 8;
#pragma unroll
        for (int j = 0; j < 4; j++) {
            int col = n0 + wn + j * 8 + q2;
            float b0 = bias[col], b1 = bias[col + 1];
            float v00 = acc[mi][j][0] + b0, v01 = acc[mi][j][1] + b1;
            float v10 = acc[mi][j][2] + b0, v11 = acc[mi][j][3] + b1;
            if (mode == 0) {
                __half* o = (__half*)out;
                int head = col >> 6, c64 = col & 63;
                *(__half2*)&o[((size_t)head * PTOK + rowa) * HD + c64] = __floats2half2_rn(v00, v01);
                *(__half2*)&o[((size_t)head * PTOK + rowb) * HD + c64] = __floats2half2_rn(v10, v11);
            } else {
                float* o = (float*)out;
                *(float2*)&o[(size_t)rowa * CDIM + col] = make_float2(v00, v01);
                *(float2*)&o[(size_t)rowb * CDIM + col] = make_float2(v10, v11);
            }
        }
    }
}

// ---------------------------------------------------------------------------
// rel_h / rel_w precompute (reads fp16 q, fp32 math, pre-scaled by log2e)
// ---------------------------------------------------------------------------
__global__ void relpos_kernel(const float* __restrict__ rph,
                              const float* __restrict__ rpw)
{
    const int b = blockIdx.x;
    const int n = b >> 12;
    const int p = b & 4095;
    const int h = p >> 6, w = p & 63;
    const int t = threadIdx.x;

    __shared__ float qs[64];
    qs[t] = __half2float(g_qh[((size_t)n * PTOK + p) * HD + t]);
    __syncthreads();

    const float* rh = rph + (size_t)(h - t + 63) * HD;
    const float* rw = rpw + (size_t)(w - t + 63) * HD;
    float sh = 0.f, sw = 0.f;
#pragma unroll
    for (int c = 0; c < HD; c++) {
        float qc = qs[c];
        sh += qc * rh[c];
        sw += qc * rw[c];
    }
    g_relh[((size_t)n * PTOK + p) * HD + t] = sh * LOG2E;
    g_relw[((size_t)n * PTOK + p) * HD + t] = sw * LOG2E;
}

// ---------------------------------------------------------------------------
// Flash attention, fp16 tensor cores, base-2 online softmax.
// Grid (32 qtiles, 12 heads), 256 threads (8 warps), 128 queries per block,
// each warp owns 16 query rows. Bias (reference broadcast quirk):
//   rel_h term: per-row scalar  g_relh[n][p][kb]
//   rel_w term: per-col scalar  g_relw[n][qh*64+kb][col]  (qh const per warp)
// ---------------------------------------------------------------------------
__global__ __launch_bounds__(256) void flash_kernel(float scale2)
{
    __shared__ __half Qs[128 * 72];
    __shared__ __half Ks[64 * 72];
    __shared__ __half Vs[64 * 72];

    const int n  = blockIdx.y;
    const int qb = blockIdx.x;
    const int tid = threadIdx.x;
    const int warp = tid >> 5, lane = tid & 31;
    const int r0l = lane >> 2, q2 = (lane & 3) * 2;

    const __half* qbase = g_qh + ((size_t)n * PTOK + qb * 128) * HD;
#pragma unroll
    for (int i = 0; i < 4; i++) {
        int v = tid + i * 256;
        int r = v >> 3, c = (v & 7) * 8;
        *(uint4*)&Qs[r * 72 + c] = *(const uint4*)&qbase[r * HD + c];
    }
    __syncthreads();

    // Q fragments (kept in registers for the whole kernel)
    unsigned qf[4][4];
#pragma unroll
    for (int ks = 0; ks < 4; ks++) {
        unsigned addr = su32(&Qs[(warp * 16 + (lane & 15)) * 72
                                 + ks * 16 + (lane >> 4) * 8]);
        ldsm_x4(qf[ks][0], qf[ks][1], qf[ks][2], qf[ks][3], addr);
    }

    const int row0 = qb * 128 + warp * 16 + r0l;     // global query index
    const int qh   = (qb * 128 + warp * 16) >> 6;    // constant per warp
    const float* rh_base = g_relh + (size_t)n * PTOK * HD;
    const float* rw_base = g_relw + ((size_t)n * PTOK + qh * 64) * HD;

    float m0 = -1e30f, m1 = -1e30f, l0 = 0.f, l1 = 0.f;
    float o[8][4] = {};

    for (int kb = 0; kb < 64; kb++) {
        const __half* kp = g_kh + ((size_t)n * PTOK + kb * 64) * HD;
        const __half* vp = g_vh + ((size_t)n * PTOK + kb * 64) * HD;
        __syncthreads();
#pragma unroll
        for (int i = 0; i < 2; i++) {
            int v = tid + i * 256;
            int r = v >> 3, c = (v & 7) * 8;
            *(uint4*)&Ks[r * 72 + c] = *(const uint4*)&kp[r * HD + c];
            *(uint4*)&Vs[r * 72 + c] = *(const uint4*)&vp[r * HD + c];
        }
        __syncthreads();

        // S = Q K^T   (16 x 64 per warp)
        float s[8][4] = {};
#pragma unroll
        for (int ks = 0; ks < 4; ks++) {
#pragma unroll
            for (int j = 0; j < 8; j++) {
                unsigned b0, b1;
                unsigned addr = su32(&Ks[(j * 8 + (lane & 7)) * 72
                                         + ks * 16 + ((lane >> 3) & 1) * 8]);
                ldsm_x2(b0, b1, addr);
                mma16816(s[j], qf[ks], b0, b1);
            }
        }

        // bias + online softmax (base-2 domain)
        const float rh0 = rh_base[(size_t)row0 * HD + kb];
        const float rh1 = rh_base[(size_t)(row0 + 8) * HD + kb];
        const float* rwr = rw_base + (size_t)kb * HD;
        float mx0 = -1e30f, mx1 = -1e30f;
#pragma unroll
        for (int j = 0; j < 8; j++) {
            float2 rw = *(const float2*)&rwr[j * 8 + q2];
            s[j][0] = s[j][0] * scale2 + rh0 + rw.x;
            s[j][1] = s[j][1] * scale2 + rh0 + rw.y;
            s[j][2] = s[j][2] * scale2 + rh1 + rw.x;
            s[j][3] = s[j][3] * scale2 + rh1 + rw.y;
            mx0 = fmaxf(mx0, fmaxf(s[j][0], s[j][1]));
            mx1 = fmaxf(mx1, fmaxf(s[j][2], s[j][3]));
        }
#pragma unroll
        for (int off = 1; off <= 2; off <<= 1) {
            mx0 = fmaxf(mx0, __shfl_xor_sync(0xffffffffu, mx0, off));
            mx1 = fmaxf(mx1, __shfl_xor_sync(0xffffffffu, mx1, off));
        }
        float nm0 = fmaxf(m0, mx0), nm1 = fmaxf(m1, mx1);
        float c0 = ex2(m0 - nm0), c1 = ex2(m1 - nm1);
        float sum0 = 0.f, sum1 = 0.f;
#pragma unroll
        for (int j = 0; j < 8; j++) {
            s[j][0] = ex2(s[j][0] - nm0);
            s[j][1] = ex2(s[j][1] - nm0);
            s[j][2] = ex2(s[j][2] - nm1);
            s[j][3] = ex2(s[j][3] - nm1);
            sum0 += s[j][0] + s[j][1];
            sum1 += s[j][2] + s[j][3];
        }
#pragma unroll
        for (int off = 1; off <= 2; off <<= 1) {
            sum0 += __shfl_xor_sync(0xffffffffu, sum0, off);
            sum1 += __shfl_xor_sync(0xffffffffu, sum1, off);
        }
        l0 = l0 * c0 + sum0;
        l1 = l1 * c1 + sum1;
        m0 = nm0; m1 = nm1;
#pragma unroll
        for (int j = 0; j < 8; j++) {
            o[j][0] *= c0; o[j][1] *= c0;
            o[j][2] *= c1; o[j][3] *= c1;
        }

        // P fragments (register-only C->A relayout)
        unsigned pf[4][4];
#pragma unroll
        for (int kk = 0; kk < 4; kk++) {
            pf[kk][0] = pack2(s[2 * kk][0],     s[2 * kk][1]);
            pf[kk][1] = pack2(s[2 * kk][2],     s[2 * kk][3]);
            pf[kk][2] = pack2(s[2 * kk + 1][0], s[2 * kk + 1][1]);
            pf[kk][3] = pack2(s[2 * kk + 1][2], s[2 * kk + 1][3]);
        }

        // O += P V
#pragma unroll
        for (int kk = 0; kk < 4; kk++) {
#pragma unroll
            for (int j = 0; j < 8; j++) {
                unsigned b0, b1;
                unsigned addr = su32(&Vs[(kk * 16 + (lane & 15)) * 72 + j * 8]);
                ldsm_x2t(b0, b1, addr);
                mma16816(o[j], pf[kk], b0, b1);
            }
        }
    }

    // epilogue: normalize, write half to [p][n*64+d]
    float inv0 = 1.f / l0, inv1 = 1.f / l1;
#pragma unroll
    for (int j = 0; j < 8; j++) {
        int col = n * HD + j * 8 + q2;
        *(__half2*)&g_oh[(size_t)row0 * CDIM + col] =
            __floats2half2_rn(o[j][0] * inv0, o[j][1] * inv0);
        *(__half2*)&g_oh[(size_t)(row0 + 8) * CDIM + col] =
            __floats2half2_rn(o[j][2] * inv1, o[j][3] * inv1);
    }
}

// ---------------------------------------------------------------------------
extern "C" void kernel_launch(void* const* d_in, const int* in_sizes, int n_in,
                              void* d_out, int out_size)
{
    const float* x   = (const float*)d_in[0];
    const float* wq  = (const float*)d_in[1];
    const float* bq  = (const float*)d_in[2];
    const float* wk  = (const float*)d_in[3];
    const float* bk  = (const float*)d_in[4];
    const float* wv  = (const float*)d_in[5];
    const float* bv  = (const float*)d_in[6];
    const float* rph = (const float*)d_in[7];
    const float* rpw = (const float*)d_in[8];
    const float* pw  = (const float*)d_in[9];
    const float* pb  = (const float*)d_in[10];
    float* out = (float*)d_out;

    __half *hx, *hwq, *hwk, *hwv, *hpw, *qh, *kh, *vh, *oh;
    cudaGetSymbolAddress((void**)&hx,  g_hx);
    cudaGetSymbolAddress((void**)&hwq, g_hwq);
    cudaGetSymbolAddress((void**)&hwk, g_hwk);
    cudaGetSymbolAddress((void**)&hwv, g_hwv);
    cudaGetSymbolAddress((void**)&hpw, g_hpw);
    cudaGetSymbolAddress((void**)&qh,  g_qh);
    cudaGetSymbolAddress((void**)&kh,  g_kh);
    cudaGetSymbolAddress((void**)&vh,  g_vh);
    cudaGetSymbolAddress((void**)&oh,  g_oh);

    const int NX = PTOK * CDIM;       // 3145728
    const int NW = CDIM * CDIM;       // 589824
    f2h_kernel<<<NX / 1024, 256>>>(x,  hx,  NX);
    f2h_kernel<<<NW / 1024, 256>>>(wq, hwq, NW);
    f2h_kernel<<<NW / 1024, 256>>>(wk, hwk, NW);
    f2h_kernel<<<NW / 1024, 256>>>(wv, hwv, NW);
    f2h_kernel<<<NW / 1024, 256>>>(pw, hpw, NW);

    dim3 ggrid(CDIM / 64, PTOK / 128);   // (12, 32)
    hgemm_kernel<<<ggrid, 256>>>(hx, hwq, bq, qh, 0);
    hgemm_kernel<<<ggrid, 256>>>(hx, hwk, bk, kh, 0);
    hgemm_kernel<<<ggrid, 256>>>(hx, hwv, bv, vh, 0);

    relpos_kernel<<<NH * PTOK, 64>>>(rph, rpw);

    flash_kernel<<<dim3(32, NH), 256>>>(0.125f * LOG2E);

    hgemm_kernel<<<ggrid, 256>>>(oh, hpw, pb, out, 1);
}

// round 6
// speedup vs baseline: 10.0054x; 4.6209x over previous
#include <cuda_runtime.h>
#include <cuda_fp16.h>
#include <cuda_bf16.h>

// Problem constants: B=1, H=W=64 (P=4096 tokens), C=768, nH=12, hd=64.
#define PTOK 4096
#define CDIM 768
#define NH   12
#define HD   64
#define LOG2E 1.44269504088896f

// ---------------------------------------------------------------------------
// Scratch (__device__ globals; no cudaMalloc allowed)
// ---------------------------------------------------------------------------
__device__ __half g_hx [PTOK * CDIM];       // x in fp16
__device__ __half g_hwq[CDIM * CDIM];
__device__ __half g_hwk[CDIM * CDIM];
__device__ __half g_hwv[CDIM * CDIM];
__device__ __half g_hpw[CDIM * CDIM];
__device__ __half g_qh [NH * PTOK * HD];    // per-head q/k/v fp16
__device__ __half g_kh [NH * PTOK * HD];
__device__ __half g_vh [NH * PTOK * HD];
__device__ __half g_oh [PTOK * CDIM];       // attention out [p][n*64+d]
__device__ float  g_relh[NH * PTOK * HD];   // [n][p][kh]  (pre-scaled by log2e)
__device__ float  g_relw[NH * PTOK * HD];   // [n][p][kw]

// ---------------------------------------------------------------------------
// helpers
// ---------------------------------------------------------------------------
__device__ __forceinline__ unsigned su32(const void* p) {
    return (unsigned)__cvta_generic_to_shared(p);
}
__device__ __forceinline__ void ldsm_x4(unsigned& r0, unsigned& r1,
                                        unsigned& r2, unsigned& r3, unsigned a) {
    asm volatile("ldmatrix.sync.aligned.m8n8.x4.shared.b16 {%0,%1,%2,%3}, [%4];"
                 : "=r"(r0), "=r"(r1), "=r"(r2), "=r"(r3) : "r"(a));
}
__device__ __forceinline__ void ldsm_x4t(unsigned& r0, unsigned& r1,
                                         unsigned& r2, unsigned& r3, unsigned a) {
    asm volatile("ldmatrix.sync.aligned.m8n8.x4.trans.shared.b16 {%0,%1,%2,%3}, [%4];"
                 : "=r"(r0), "=r"(r1), "=r"(r2), "=r"(r3) : "r"(a));
}
__device__ __forceinline__ void mma16816(float* c, const unsigned* a,
                                         unsigned b0, unsigned b1) {
    asm volatile(
        "mma.sync.aligned.m16n8k16.row.col.f32.f16.f16.f32 "
        "{%0,%1,%2,%3},{%4,%5,%6,%7},{%8,%9},{%0,%1,%2,%3};"
        : "+f"(c[0]), "+f"(c[1]), "+f"(c[2]), "+f"(c[3])
        : "r"(a[0]), "r"(a[1]), "r"(a[2]), "r"(a[3]), "r"(b0), "r"(b1));
}
__device__ __forceinline__ float ex2(float x) {
    float r; asm("ex2.approx.f32 %0, %1;" : "=f"(r) : "f"(x)); return r;
}
__device__ __forceinline__ unsigned pack2(float x, float y) {
    __half2 h = __floats2half2_rn(x, y);
    return *reinterpret_cast<unsigned*>(&h);
}
__device__ __forceinline__ void cpa16(unsigned dst, const void* src) {
    asm volatile("cp.async.cg.shared.global [%0], [%1], 16;"
                 :: "r"(dst), "l"(src) : "memory");
}
#define CP_COMMIT asm volatile("cp.async.commit_group;" ::: "memory")
#define CP_WAIT0  asm volatile("cp.async.wait_group 0;" ::: "memory")

// ---------------------------------------------------------------------------
// fp32 -> fp16 conversion (4 elems/thread)
// ---------------------------------------------------------------------------
__global__ void f2h_kernel(const float* __restrict__ in, __half* __restrict__ out, int n)
{
    int i = (blockIdx.x * 256 + threadIdx.x) * 4;
    if (i < n) {
        float4 v = *(const float4*)(in + i);
        *(__half2*)(out + i)     = __floats2half2_rn(v.x, v.y);
        *(__half2*)(out + i + 2) = __floats2half2_rn(v.z, v.w);
    }
}

// ---------------------------------------------------------------------------
// fp16 tensor-core GEMM: out[m][o] = sum_c A[m][c] * W[o][c] + bias[o]
// mode 0: half out, per-head layout [(o>>6)*P + m][o&63]
// mode 1: fp32 out, plain [m][768]
// ---------------------------------------------------------------------------
__global__ __launch_bounds__(256) void hgemm_kernel(
    const __half* __restrict__ A, const __half* __restrict__ W,
    const float* __restrict__ bias, void* __restrict__ out, int mode)
{
    __shared__ __half As[128 * 40];
    __shared__ __half Bs[64 * 40];
    const int tid = threadIdx.x;
    const int warp = tid >> 5, lane = tid & 31;
    const int m0 = blockIdx.y * 128;
    const int n0 = blockIdx.x * 64;
    const int wm = (warp >> 1) * 32;
    const int wn = (warp & 1) * 32;

    float acc[2][4][4] = {};

    for (int k0 = 0; k0 < CDIM; k0 += 32) {
#pragma unroll
        for (int i = 0; i < 2; i++) {
            int v = tid + i * 256;
            int r = v >> 2, c = (v & 3) * 8;
            *(uint4*)&As[r * 40 + c] = *(const uint4*)&A[(size_t)(m0 + r) * CDIM + k0 + c];
        }
        {
            int r = tid >> 2, c = (tid & 3) * 8;
            *(uint4*)&Bs[r * 40 + c] = *(const uint4*)&W[(size_t)(n0 + r) * CDIM + k0 + c];
        }
        __syncthreads();
#pragma unroll
        for (int ks = 0; ks < 2; ks++) {
            unsigned a[2][4];
#pragma unroll
            for (int mi = 0; mi < 2; mi++) {
                unsigned addr = su32(&As[(wm + mi * 16 + (lane & 15)) * 40
                                         + ks * 16 + (lane >> 4) * 8]);
                ldsm_x4(a[mi][0], a[mi][1], a[mi][2], a[mi][3], addr);
            }
#pragma unroll
            for (int j2 = 0; j2 < 2; j2++) {
                unsigned b0, b1, b2, b3;
                unsigned addr = su32(&Bs[(wn + j2 * 16 + (lane & 15)) * 40
                                         + ks * 16 + (lane >> 4) * 8]);
                ldsm_x4(b0, b1, b2, b3, addr);
#pragma unroll
                for (int mi = 0; mi < 2; mi++) {
                    mma16816(acc[mi][2 * j2],     a[mi], b0, b2);
                    mma16816(acc[mi][2 * j2 + 1], a[mi], b1, b3);
                }
            }
        }
        __syncthreads();
    }

    const int r0 = lane >> 2, q2 = (lane & 3) * 2;
#pragma unroll
    for (int mi = 0; mi < 2; mi++) {
        int rowa = m0 + wm + mi * 16 + r0;
        int rowb = rowa + 8;
#pragma unroll
        for (int j = 0; j < 4; j++) {
            int col = n0 + wn + j * 8 + q2;
            float b0 = bias[col], b1 = bias[col + 1];
            float v00 = acc[mi][j][0] + b0, v01 = acc[mi][j][1] + b1;
            float v10 = acc[mi][j][2] + b0, v11 = acc[mi][j][3] + b1;
            if (mode == 0) {
                __half* o = (__half*)out;
                int head = col >> 6, c64 = col & 63;
                *(__half2*)&o[((size_t)head * PTOK + rowa) * HD + c64] = __floats2half2_rn(v00, v01);
                *(__half2*)&o[((size_t)head * PTOK + rowb) * HD + c64] = __floats2half2_rn(v10, v11);
            } else {
                float* o = (float*)out;
                *(float2*)&o[(size_t)rowa * CDIM + col] = make_float2(v00, v01);
                *(float2*)&o[(size_t)rowb * CDIM + col] = make_float2(v10, v11);
            }
        }
    }
}

// ---------------------------------------------------------------------------
// rel_h / rel_w via tensor cores. Grid (64 groups, 12 heads, 2 modes), 128 thr.
// mode 0 (rel_h): group g = qh.  A rows r = qw (contiguous rows of g_qh).
//                 B[t] = rph[g - t + 63].  out row p = g*64 + r.
// mode 1 (rel_w): group g = qw.  A rows r = qh (stride 64 rows of g_qh).
//                 B[t] = rpw[g - t + 63].  out row p = r*64 + g.
// C[r][t] = A[r] . B[t], written *LOG2E as fp32.
// ---------------------------------------------------------------------------
__global__ __launch_bounds__(128) void relpos_mma_kernel(
    const float* __restrict__ rph, const float* __restrict__ rpw)
{
    __shared__ __half As[64 * 72];
    __shared__ __half Bs[64 * 72];
    const int g = blockIdx.x, n = blockIdx.y, mode = blockIdx.z;
    const int tid = threadIdx.x, warp = tid >> 5, lane = tid & 31;

    const float* table = mode ? rpw : rph;
    const __half* qb = g_qh + ((size_t)n * PTOK + (mode ? g : g * 64)) * HD;
    const int rowstride = mode ? 64 * HD : HD;

#pragma unroll
    for (int i = 0; i < 4; i++) {            // A: 64x64 half
        int v = tid + i * 128;
        int r = v >> 3, c = (v & 7) * 8;
        *(uint4*)&As[r * 72 + c] = *(const uint4*)&qb[(size_t)r * rowstride + c];
    }
#pragma unroll
    for (int i = 0; i < 8; i++) {            // B: 64x64 fp32 table -> half
        int v = tid + i * 128;
        int t = v >> 4, c = (v & 15) * 4;
        float4 f = *(const float4*)&table[(size_t)(g - t + 63) * HD + c];
        *(__half2*)&Bs[t * 72 + c]     = __floats2half2_rn(f.x, f.y);
        *(__half2*)&Bs[t * 72 + c + 2] = __floats2half2_rn(f.z, f.w);
    }
    __syncthreads();

    unsigned qf[4][4];
#pragma unroll
    for (int ks = 0; ks < 4; ks++) {
        unsigned addr = su32(&As[(warp * 16 + (lane & 15)) * 72
                                 + ks * 16 + (lane >> 4) * 8]);
        ldsm_x4(qf[ks][0], qf[ks][1], qf[ks][2], qf[ks][3], addr);
    }

    float s[8][4] = {};
#pragma unroll
    for (int ks = 0; ks < 4; ks++) {
#pragma unroll
        for (int j2 = 0; j2 < 4; j2++) {
            unsigned b0, b1, b2, b3;
            unsigned addr = su32(&Bs[(j2 * 16 + (lane & 15)) * 72
                                     + ks * 16 + (lane >> 4) * 8]);
            ldsm_x4(b0, b1, b2, b3, addr);
            mma16816(s[2 * j2],     qf[ks], b0, b2);
            mma16816(s[2 * j2 + 1], qf[ks], b1, b3);
        }
    }

    const int r0 = lane >> 2, q2 = (lane & 3) * 2;
    const int ra = warp * 16 + r0, rb = ra + 8;
    float* outb = mode ? g_relw : g_relh;
    const size_t pa = (size_t)n * PTOK + (mode ? ra * 64 + g : g * 64 + ra);
    const size_t pb = (size_t)n * PTOK + (mode ? rb * 64 + g : g * 64 + rb);
#pragma unroll
    for (int j = 0; j < 8; j++) {
        int t = j * 8 + q2;
        *(float2*)&outb[pa * HD + t] = make_float2(s[j][0] * LOG2E, s[j][1] * LOG2E);
        *(float2*)&outb[pb * HD + t] = make_float2(s[j][2] * LOG2E, s[j][3] * LOG2E);
    }
}

// ---------------------------------------------------------------------------
// Flash attention, fp16 tensor cores, base-2 online softmax,
// cp.async double-buffered K/V, x4 ldmatrix fragments.
// Grid (32 qtiles, 12 heads), 256 threads; warp owns 16 query rows.
// Smem overlay: Q region reused by K/V buffer 1 after fragment extraction.
// ---------------------------------------------------------------------------
__global__ __launch_bounds__(256) void flash_kernel(float scale2)
{
    __shared__ __half sm[18432];   // 36 KB
    // buffer 0: K @ 9216, V @ 13824 (disjoint from Q)
    // buffer 1: K @ 0,    V @ 4608  (overlays Q; first written during kb=0)
    const int n  = blockIdx.y;
    const int qb = blockIdx.x;
    const int tid = threadIdx.x;
    const int warp = tid >> 5, lane = tid & 31;
    const int r0l = lane >> 2, q2 = (lane & 3) * 2;

    // prefetch K/V block 0 into buffer 0
    {
        const __half* kp = g_kh + ((size_t)n * PTOK) * HD;
        const __half* vp = g_vh + ((size_t)n * PTOK) * HD;
        __half* kd = sm + 9216;
        __half* vd = sm + 13824;
#pragma unroll
        for (int i = 0; i < 2; i++) {
            int v = tid + i * 256;
            int r = v >> 3, c = (v & 7) * 8;
            cpa16(su32(&kd[r * 72 + c]), kp + r * HD + c);
            cpa16(su32(&vd[r * 72 + c]), vp + r * HD + c);
        }
        CP_COMMIT;
    }

    // load Q tile into sm[0..9216)
    const __half* qbase = g_qh + ((size_t)n * PTOK + qb * 128) * HD;
#pragma unroll
    for (int i = 0; i < 4; i++) {
        int v = tid + i * 256;
        int r = v >> 3, c = (v & 7) * 8;
        *(uint4*)&sm[r * 72 + c] = *(const uint4*)&qbase[r * HD + c];
    }
    __syncthreads();

    unsigned qf[4][4];
#pragma unroll
    for (int ks = 0; ks < 4; ks++) {
        unsigned addr = su32(&sm[(warp * 16 + (lane & 15)) * 72
                                 + ks * 16 + (lane >> 4) * 8]);
        ldsm_x4(qf[ks][0], qf[ks][1], qf[ks][2], qf[ks][3], addr);
    }

    const int row0 = qb * 128 + warp * 16 + r0l;
    const int qh   = (qb * 128 + warp * 16) >> 6;
    const float* rh_base = g_relh + (size_t)n * PTOK * HD;
    const float* rw_base = g_relw + ((size_t)n * PTOK + qh * 64) * HD;

    float m0 = -1e30f, m1 = -1e30f, l0 = 0.f, l1 = 0.f;
    float o[8][4] = {};

    for (int kb = 0; kb < 64; kb++) {
        CP_WAIT0;
        __syncthreads();    // kb data visible to all; prior compute done

        if (kb < 63) {      // prefetch kb+1 into other buffer
            int nb = (kb + 1) & 1;
            const __half* kp = g_kh + ((size_t)n * PTOK + (kb + 1) * 64) * HD;
            const __half* vp = g_vh + ((size_t)n * PTOK + (kb + 1) * 64) * HD;
            __half* kd = sm + (nb ? 0 : 9216);
            __half* vd = sm + (nb ? 4608 : 13824);
#pragma unroll
            for (int i = 0; i < 2; i++) {
                int v = tid + i * 256;
                int r = v >> 3, c = (v & 7) * 8;
                cpa16(su32(&kd[r * 72 + c]), kp + r * HD + c);
                cpa16(su32(&vd[r * 72 + c]), vp + r * HD + c);
            }
            CP_COMMIT;
        }

        const __half* Ks = sm + ((kb & 1) ? 0 : 9216);
        const __half* Vs = sm + ((kb & 1) ? 4608 : 13824);

        // S = Q K^T   (16 x 64 per warp)
        float s[8][4] = {};
#pragma unroll
        for (int ks = 0; ks < 4; ks++) {
#pragma unroll
            for (int j2 = 0; j2 < 4; j2++) {
                unsigned b0, b1, b2, b3;
                unsigned addr = su32(&Ks[(j2 * 16 + (lane & 15)) * 72
                                         + ks * 16 + (lane >> 4) * 8]);
                ldsm_x4(b0, b1, b2, b3, addr);
                mma16816(s[2 * j2],     qf[ks], b0, b2);
                mma16816(s[2 * j2 + 1], qf[ks], b1, b3);
            }
        }

        // bias + online softmax (base-2 domain)
        const float rh0 = rh_base[(size_t)row0 * HD + kb];
        const float rh1 = rh_base[(size_t)(row0 + 8) * HD + kb];
        const float* rwr = rw_base + (size_t)kb * HD;
        float mx0 = -1e30f, mx1 = -1e30f;
#pragma unroll
        for (int j = 0; j < 8; j++) {
            float2 rw = *(const float2*)&rwr[j * 8 + q2];
            s[j][0] = s[j][0] * scale2 + rh0 + rw.x;
            s[j][1] = s[j][1] * scale2 + rh0 + rw.y;
            s[j][2] = s[j][2] * scale2 + rh1 + rw.x;
            s[j][3] = s[j][3] * scale2 + rh1 + rw.y;
            mx0 = fmaxf(mx0, fmaxf(s[j][0], s[j][1]));
            mx1 = fmaxf(mx1, fmaxf(s[j][2], s[j][3]));
        }
#pragma unroll
        for (int off = 1; off <= 2; off <<= 1) {
            mx0 = fmaxf(mx0, __shfl_xor_sync(0xffffffffu, mx0, off));
            mx1 = fmaxf(mx1, __shfl_xor_sync(0xffffffffu, mx1, off));
        }
        float nm0 = fmaxf(m0, mx0), nm1 = fmaxf(m1, mx1);
        float c0 = ex2(m0 - nm0), c1 = ex2(m1 - nm1);
        float sum0 = 0.f, sum1 = 0.f;
#pragma unroll
        for (int j = 0; j < 8; j++) {
            s[j][0] = ex2(s[j][0] - nm0);
            s[j][1] = ex2(s[j][1] - nm0);
            s[j][2] = ex2(s[j][2] - nm1);
            s[j][3] = ex2(s[j][3] - nm1);
            sum0 += s[j][0] + s[j][1];
            sum1 += s[j][2] + s[j][3];
        }
#pragma unroll
        for (int off = 1; off <= 2; off <<= 1) {
            sum0 += __shfl_xor_sync(0xffffffffu, sum0, off);
            sum1 += __shfl_xor_sync(0xffffffffu, sum1, off);
        }
        l0 = l0 * c0 + sum0;
        l1 = l1 * c1 + sum1;
        m0 = nm0; m1 = nm1;
#pragma unroll
        for (int j = 0; j < 8; j++) {
            o[j][0] *= c0; o[j][1] *= c0;
            o[j][2] *= c1; o[j][3] *= c1;
        }

        // P fragments (register-only C->A relayout)
        unsigned pf[4][4];
#pragma unroll
        for (int kk = 0; kk < 4; kk++) {
            pf[kk][0] = pack2(s[2 * kk][0],     s[2 * kk][1]);
            pf[kk][1] = pack2(s[2 * kk][2],     s[2 * kk][3]);
            pf[kk][2] = pack2(s[2 * kk + 1][0], s[2 * kk + 1][1]);
            pf[kk][3] = pack2(s[2 * kk + 1][2], s[2 * kk + 1][3]);
        }

        // O += P V
#pragma unroll
        for (int kk = 0; kk < 4; kk++) {
#pragma unroll
            for (int j2 = 0; j2 < 4; j2++) {
                unsigned b0, b1, b2, b3;
                unsigned addr = su32(&Vs[(kk * 16 + (lane & 15)) * 72
                                         + j2 * 16 + (lane >> 4) * 8]);
                ldsm_x4t(b0, b1, b2, b3, addr);
                mma16816(o[2 * j2],     pf[kk], b0, b1);
                mma16816(o[2 * j2 + 1], pf[kk], b2, b3);
            }
        }
        __syncthreads();   // all reads of this buffer done before next prefetch
    }

    // epilogue: normalize, write half to [p][n*64+d]
    float inv0 = 1.f / l0, inv1 = 1.f / l1;
#pragma unroll
    for (int j = 0; j < 8; j++) {
        int col = n * HD + j * 8 + q2;
        *(__half2*)&g_oh[(size_t)row0 * CDIM + col] =
            __floats2half2_rn(o[j][0] * inv0, o[j][1] * inv0);
        *(__half2*)&g_oh[(size_t)(row0 + 8) * CDIM + col] =
            __floats2half2_rn(o[j][2] * inv1, o[j][3] * inv1);
    }
}

// ---------------------------------------------------------------------------
extern "C" void kernel_launch(void* const* d_in, const int* in_sizes, int n_in,
                              void* d_out, int out_size)
{
    const float* x   = (const float*)d_in[0];
    const float* wq  = (const float*)d_in[1];
    const float* bq  = (const float*)d_in[2];
    const float* wk  = (const float*)d_in[3];
    const float* bk  = (const float*)d_in[4];
    const float* wv  = (const float*)d_in[5];
    const float* bv  = (const float*)d_in[6];
    const float* rph = (const float*)d_in[7];
    const float* rpw = (const float*)d_in[8];
    const float* pw  = (const float*)d_in[9];
    const float* pb  = (const float*)d_in[10];
    float* out = (float*)d_out;

    __half *hx, *hwq, *hwk, *hwv, *hpw, *qh, *kh, *vh, *oh;
    cudaGetSymbolAddress((void**)&hx,  g_hx);
    cudaGetSymbolAddress((void**)&hwq, g_hwq);
    cudaGetSymbolAddress((void**)&hwk, g_hwk);
    cudaGetSymbolAddress((void**)&hwv, g_hwv);
    cudaGetSymbolAddress((void**)&hpw, g_hpw);
    cudaGetSymbolAddress((void**)&qh,  g_qh);
    cudaGetSymbolAddress((void**)&kh,  g_kh);
    cudaGetSymbolAddress((void**)&vh,  g_vh);
    cudaGetSymbolAddress((void**)&oh,  g_oh);

    const int NX = PTOK * CDIM;
    const int NW = CDIM * CDIM;
    f2h_kernel<<<NX / 1024, 256>>>(x,  hx,  NX);
    f2h_kernel<<<NW / 1024, 256>>>(wq, hwq, NW);
    f2h_kernel<<<NW / 1024, 256>>>(wk, hwk, NW);
    f2h_kernel<<<NW / 1024, 256>>>(wv, hwv, NW);
    f2h_kernel<<<NW / 1024, 256>>>(pw, hpw, NW);

    dim3 ggrid(CDIM / 64, PTOK / 128);   // (12, 32)
    hgemm_kernel<<<ggrid, 256>>>(hx, hwq, bq, qh, 0);
    hgemm_kernel<<<ggrid, 256>>>(hx, hwk, bk, kh, 0);
    hgemm_kernel<<<ggrid, 256>>>(hx, hwv, bv, vh, 0);

    relpos_mma_kernel<<<dim3(64, NH, 2), 128>>>(rph, rpw);

    flash_kernel<<<dim3(32, NH), 256>>>(0.125f * LOG2E);

    hgemm_kernel<<<ggrid, 256>>>(oh, hpw, pb, out, 1);
}